// round 1
// baseline (speedup 1.0000x reference)
#include <cuda_runtime.h>
#include <math.h>

// Scratch: per-(node, head) exp-sum accumulator. N*H = 200K for this problem;
// 4M floats (16 MB) gives generous margin. Static __device__ => no allocation.
#define MAX_S (4 * 1024 * 1024)
__device__ float g_s[MAX_S];

__device__ __forceinline__ float softplus_f(float x) {
    // x is ~1.0 here; plain accurate path.
    return log1pf(expf(x));
}

// ---------------------------------------------------------------------------
// Kernel A: zero scratch + output
// ---------------------------------------------------------------------------
__global__ void init_kernel(float* __restrict__ out, int out_size, int s_count) {
    int i = blockIdx.x * blockDim.x + threadIdx.x;
    if (i < s_count) g_s[i] = 0.0f;
    if (i < out_size) out[i] = 0.0f;
}

// ---------------------------------------------------------------------------
// Kernel B (specialized H=4, D=32): one thread per (edge, head).
// Gathers 128B of Q and 128B of K as float4s, dot, exp, atomicAdd.
// ---------------------------------------------------------------------------
__global__ void edge_kernel_s(const float* __restrict__ Q,
                              const float* __restrict__ K,
                              const float* __restrict__ a,
                              const float* __restrict__ beta_raw,
                              const int* __restrict__ c,
                              const int* __restrict__ u,
                              int E) {
    int tid = blockIdx.x * blockDim.x + threadIdx.x;
    int total = E * 4;
    if (tid >= total) return;
    int e = tid >> 2;
    int h = tid & 3;

    int ci = c[e];
    int ui = u[e];

    const float4* q = reinterpret_cast<const float4*>(Q) + (size_t)ci * 32 + h * 8;
    const float4* k = reinterpret_cast<const float4*>(K) + (size_t)ui * 32 + h * 8;

    float acc = 0.0f;
#pragma unroll
    for (int i = 0; i < 8; i++) {
        float4 A = q[i];
        float4 B = k[i];
        acc = fmaf(A.x, B.x, acc);
        acc = fmaf(A.y, B.y, acc);
        acc = fmaf(A.z, B.z, acc);
        acc = fmaf(A.w, B.w, acc);
    }

    float beta = fminf(softplus_f(beta_raw[0]), 10.0f);
    // scale = sqrt(32); 1/sqrt(32)
    float ell = acc * 0.17677669529663688f + a[h];
    atomicAdd(&g_s[(size_t)ci * 4 + h], __expf(beta * ell));
}

// Generic fallback (any H, D)
__global__ void edge_kernel_g(const float* __restrict__ Q,
                              const float* __restrict__ K,
                              const float* __restrict__ a,
                              const float* __restrict__ beta_raw,
                              const int* __restrict__ c,
                              const int* __restrict__ u,
                              int E, int H, int D) {
    int tid = blockIdx.x * blockDim.x + threadIdx.x;
    int total = E * H;
    if (tid >= total) return;
    int e = tid / H;
    int h = tid % H;

    int ci = c[e];
    int ui = u[e];

    const float* q = Q + ((size_t)ci * H + h) * D;
    const float* k = K + ((size_t)ui * H + h) * D;
    float acc = 0.0f;
    for (int d = 0; d < D; d++) acc = fmaf(q[d], k[d], acc);

    float beta = fminf(softplus_f(beta_raw[0]), 10.0f);
    float ell = acc * rsqrtf((float)D) + a[h];
    atomicAdd(&g_s[(size_t)ci * H + h], __expf(beta * ell));
}

// ---------------------------------------------------------------------------
// Kernel C (specialized H=4): one thread per node.
// lse = log(s) if s>0 else 0; scatter (lam/beta)*lse into out[batch[n]*H+h].
// ---------------------------------------------------------------------------
__global__ void node_kernel_s(const int* __restrict__ batch,
                              const float* __restrict__ lam_raw,
                              const float* __restrict__ beta_raw,
                              float* __restrict__ out,
                              int N) {
    int n = blockIdx.x * blockDim.x + threadIdx.x;
    if (n >= N) return;

    float lam  = softplus_f(lam_raw[0]);
    float beta = fminf(softplus_f(beta_raw[0]), 10.0f);
    float coef = lam / beta;

    float4 sv = reinterpret_cast<const float4*>(g_s)[n];
    int g = batch[n];
    float v0 = sv.x > 0.0f ? logf(sv.x) : 0.0f;
    float v1 = sv.y > 0.0f ? logf(sv.y) : 0.0f;
    float v2 = sv.z > 0.0f ? logf(sv.z) : 0.0f;
    float v3 = sv.w > 0.0f ? logf(sv.w) : 0.0f;
    atomicAdd(&out[g * 4 + 0], coef * v0);
    atomicAdd(&out[g * 4 + 1], coef * v1);
    atomicAdd(&out[g * 4 + 2], coef * v2);
    atomicAdd(&out[g * 4 + 3], coef * v3);
}

__global__ void node_kernel_g(const int* __restrict__ batch,
                              const float* __restrict__ lam_raw,
                              const float* __restrict__ beta_raw,
                              float* __restrict__ out,
                              int N, int H) {
    int n = blockIdx.x * blockDim.x + threadIdx.x;
    if (n >= N) return;

    float lam  = softplus_f(lam_raw[0]);
    float beta = fminf(softplus_f(beta_raw[0]), 10.0f);
    float coef = lam / beta;

    int g = batch[n];
    for (int h = 0; h < H; h++) {
        float s = g_s[(size_t)n * H + h];
        float v = s > 0.0f ? logf(s) : 0.0f;
        atomicAdd(&out[g * H + h], coef * v);
    }
}

// ---------------------------------------------------------------------------
// Launch
// Inputs (metadata order, from reference setup_inputs):
//   0: G            [4,4]      f32 (unused)
//   1: Q2           [N,H,D]    f32
//   2: K2           [N,H,D]    f32
//   3: a_2          [H]        f32
//   4: lambda_2_raw [1]        f32
//   5: beta_2_raw   [1]        f32
//   6: c_2          [E]        i32
//   7: u_2          [E]        i32
//   8: batch        [N]        i32
//   (num_graphs/num_nodes derived from sizes)
// Output: [num_graphs, H] f32
// ---------------------------------------------------------------------------
extern "C" void kernel_launch(void* const* d_in, const int* in_sizes, int n_in,
                              void* d_out, int out_size) {
    const float* Q        = (const float*)d_in[1];
    const float* K        = (const float*)d_in[2];
    const float* a        = (const float*)d_in[3];
    const float* lam_raw  = (const float*)d_in[4];
    const float* beta_raw = (const float*)d_in[5];
    const int*   c        = (const int*)d_in[6];
    const int*   u        = (const int*)d_in[7];
    const int*   batch    = (const int*)d_in[8];
    float*       out      = (float*)d_out;

    int H = in_sizes[3];                 // 4
    int E = in_sizes[6];                 // 1.6M
    int N = in_sizes[8];                 // 50000
    int D = (int)((long long)in_sizes[1] / ((long long)N * H)); // 32

    int s_count = N * H;
    if (s_count > MAX_S) return;  // out of scratch budget (shouldn't happen)

    const int TB = 256;

    // A: init scratch + out
    {
        int work = s_count > out_size ? s_count : out_size;
        init_kernel<<<(work + TB - 1) / TB, TB>>>(out, out_size, s_count);
    }

    // B: edge pass
    if (H == 4 && D == 32) {
        long long total = (long long)E * 4;
        edge_kernel_s<<<(int)((total + TB - 1) / TB), TB>>>(Q, K, a, beta_raw, c, u, E);
    } else {
        long long total = (long long)E * H;
        edge_kernel_g<<<(int)((total + TB - 1) / TB), TB>>>(Q, K, a, beta_raw, c, u, E, H, D);
    }

    // C: node pass
    if (H == 4) {
        node_kernel_s<<<(N + TB - 1) / TB, TB>>>(batch, lam_raw, beta_raw, out, N);
    } else {
        node_kernel_g<<<(N + TB - 1) / TB, TB>>>(batch, lam_raw, beta_raw, out, N, H);
    }
}

// round 3
// speedup vs baseline: 2.3523x; 2.3523x over previous
#include <cuda_runtime.h>
#include <cuda_fp16.h>
#include <stdint.h>
#include <math.h>

// ---------------------------------------------------------------------------
// Static scratch (no runtime allocation allowed).
//   g_s : per-(node,head) exp-sum accumulator (float)
//   g_qh/g_kh : half-precision copies of Q2/K2 for bandwidth-halved gathers
// N*H = 200K, N*H*D = 6.4M for this problem; sizes below give margin.
// ---------------------------------------------------------------------------
#define MAX_S   (4 * 1024 * 1024)
#define MAX_NHD (8 * 1024 * 1024)
__device__ float  g_s[MAX_S];
__device__ __half g_qh[MAX_NHD];
__device__ __half g_kh[MAX_NHD];

__device__ __forceinline__ float softplus_f(float x) {
    return log1pf(expf(x));
}

__device__ __forceinline__ unsigned int h2_bits(__half2 h) {
    union { __half2 h2; unsigned int u; } cvt;
    cvt.h2 = h;
    return cvt.u;
}

// ---------------------------------------------------------------------------
// Kernel A: zero scratch + output
// ---------------------------------------------------------------------------
__global__ void init_kernel(float* __restrict__ out, int out_size, int s_count) {
    int i = blockIdx.x * blockDim.x + threadIdx.x;
    if (i < s_count) g_s[i] = 0.0f;
    if (i < out_size) out[i] = 0.0f;
}

// ---------------------------------------------------------------------------
// Kernel A2: convert Q/K f32 -> f16 scratch. Each thread handles 4 elems of
// both arrays (float4 load -> 2x half2 packed as uint2 store).
// ---------------------------------------------------------------------------
__global__ void convert_kernel(const float* __restrict__ Q,
                               const float* __restrict__ K,
                               int total4 /* = N*H*D/4 */) {
    int i = blockIdx.x * blockDim.x + threadIdx.x;
    if (i >= total4) return;
    float4 q = reinterpret_cast<const float4*>(Q)[i];
    float4 k = reinterpret_cast<const float4*>(K)[i];
    uint2 qp, kp;
    qp.x = h2_bits(__floats2half2_rn(q.x, q.y));
    qp.y = h2_bits(__floats2half2_rn(q.z, q.w));
    kp.x = h2_bits(__floats2half2_rn(k.x, k.y));
    kp.y = h2_bits(__floats2half2_rn(k.z, k.w));
    reinterpret_cast<uint2*>(g_qh)[i] = qp;
    reinterpret_cast<uint2*>(g_kh)[i] = kp;
}

// ---------------------------------------------------------------------------
// Kernel B (H=4, D=32): half-warp per edge.
// Row = 128 halves = 256B. Lane lw in [0,16) loads 16B (8 halves) of Q and K
// at contiguous offsets -> each warp LDG touches only ~4 lines (2 edges x 2
// rows) instead of up to 32 scattered lines in the per-thread version.
// lw covers head h = lw>>2, elems d = (lw&3)*8 .. +7. Quad butterfly reduce
// gives the per-head dot; quad leader does exp + atomicAdd.
// ---------------------------------------------------------------------------
__global__ void edge_kernel_h(const float* __restrict__ a,
                              const float* __restrict__ beta_raw,
                              const int* __restrict__ c,
                              const int* __restrict__ u,
                              int E) {
    int warp = (blockIdx.x * blockDim.x + threadIdx.x) >> 5;
    int lane = threadIdx.x & 31;
    int half_sel = lane >> 4;     // which edge of the pair
    int lw = lane & 15;           // lane within half-warp

    int e = warp * 2 + half_sel;
    bool active = (e < E);
    int es = active ? e : 0;

    int ci = c[es];
    int ui = u[es];

    // 16B per lane, contiguous across the half-warp (256B = full row)
    uint4 qv = reinterpret_cast<const uint4*>(g_qh + (size_t)ci * 128)[lw];
    uint4 kv = reinterpret_cast<const uint4*>(g_kh + (size_t)ui * 128)[lw];

    float acc = 0.0f;
    const unsigned int* qw = reinterpret_cast<const unsigned int*>(&qv);
    const unsigned int* kw = reinterpret_cast<const unsigned int*>(&kv);
#pragma unroll
    for (int i = 0; i < 4; i++) {
        __half2 q2 = *reinterpret_cast<const __half2*>(&qw[i]);
        __half2 k2 = *reinterpret_cast<const __half2*>(&kw[i]);
        float2 qf = __half22float2(q2);
        float2 kf = __half22float2(k2);
        acc = fmaf(qf.x, kf.x, acc);
        acc = fmaf(qf.y, kf.y, acc);
    }

    // reduce within quad (4 lanes cover one head's 32 elems)
    acc += __shfl_xor_sync(0xffffffffu, acc, 1);
    acc += __shfl_xor_sync(0xffffffffu, acc, 2);

    if (active && (lw & 3) == 0) {
        int h = lw >> 2;
        float beta = fminf(softplus_f(beta_raw[0]), 10.0f);
        float ell = acc * 0.17677669529663688f + a[h];  // 1/sqrt(32)
        atomicAdd(&g_s[(size_t)ci * 4 + h], __expf(beta * ell));
    }
}

// Generic fallback (any H, D) — f32 path, one thread per (edge, head)
__global__ void edge_kernel_g(const float* __restrict__ Q,
                              const float* __restrict__ K,
                              const float* __restrict__ a,
                              const float* __restrict__ beta_raw,
                              const int* __restrict__ c,
                              const int* __restrict__ u,
                              int E, int H, int D) {
    long long tid = (long long)blockIdx.x * blockDim.x + threadIdx.x;
    long long total = (long long)E * H;
    if (tid >= total) return;
    int e = (int)(tid / H);
    int h = (int)(tid % H);

    int ci = c[e];
    int ui = u[e];

    const float* q = Q + ((size_t)ci * H + h) * D;
    const float* k = K + ((size_t)ui * H + h) * D;
    float acc = 0.0f;
    for (int d = 0; d < D; d++) acc = fmaf(q[d], k[d], acc);

    float beta = fminf(softplus_f(beta_raw[0]), 10.0f);
    float ell = acc * rsqrtf((float)D) + a[h];
    atomicAdd(&g_s[(size_t)ci * H + h], __expf(beta * ell));
}

// ---------------------------------------------------------------------------
// Kernel C: per-node log + scatter into per-graph output
// ---------------------------------------------------------------------------
__global__ void node_kernel_s(const int* __restrict__ batch,
                              const float* __restrict__ lam_raw,
                              const float* __restrict__ beta_raw,
                              float* __restrict__ out,
                              int N) {
    int n = blockIdx.x * blockDim.x + threadIdx.x;
    if (n >= N) return;

    float lam  = softplus_f(lam_raw[0]);
    float beta = fminf(softplus_f(beta_raw[0]), 10.0f);
    float coef = lam / beta;

    float4 sv = reinterpret_cast<const float4*>(g_s)[n];
    int g = batch[n];
    float v0 = sv.x > 0.0f ? logf(sv.x) : 0.0f;
    float v1 = sv.y > 0.0f ? logf(sv.y) : 0.0f;
    float v2 = sv.z > 0.0f ? logf(sv.z) : 0.0f;
    float v3 = sv.w > 0.0f ? logf(sv.w) : 0.0f;
    atomicAdd(&out[g * 4 + 0], coef * v0);
    atomicAdd(&out[g * 4 + 1], coef * v1);
    atomicAdd(&out[g * 4 + 2], coef * v2);
    atomicAdd(&out[g * 4 + 3], coef * v3);
}

__global__ void node_kernel_g(const int* __restrict__ batch,
                              const float* __restrict__ lam_raw,
                              const float* __restrict__ beta_raw,
                              float* __restrict__ out,
                              int N, int H) {
    int n = blockIdx.x * blockDim.x + threadIdx.x;
    if (n >= N) return;

    float lam  = softplus_f(lam_raw[0]);
    float beta = fminf(softplus_f(beta_raw[0]), 10.0f);
    float coef = lam / beta;

    int g = batch[n];
    for (int h = 0; h < H; h++) {
        float s = g_s[(size_t)n * H + h];
        float v = s > 0.0f ? logf(s) : 0.0f;
        atomicAdd(&out[g * H + h], coef * v);
    }
}

// ---------------------------------------------------------------------------
// Launch.  Inputs (metadata order):
//   0: G [4,4] f32 (unused)   1: Q2 [N,H,D] f32   2: K2 [N,H,D] f32
//   3: a_2 [H] f32   4: lambda_2_raw [1] f32   5: beta_2_raw [1] f32
//   6: c_2 [E] i32   7: u_2 [E] i32   8: batch [N] i32
// Output: [num_graphs, H] f32
// ---------------------------------------------------------------------------
extern "C" void kernel_launch(void* const* d_in, const int* in_sizes, int n_in,
                              void* d_out, int out_size) {
    const float* Q        = (const float*)d_in[1];
    const float* K        = (const float*)d_in[2];
    const float* a        = (const float*)d_in[3];
    const float* lam_raw  = (const float*)d_in[4];
    const float* beta_raw = (const float*)d_in[5];
    const int*   c        = (const int*)d_in[6];
    const int*   u        = (const int*)d_in[7];
    const int*   batch    = (const int*)d_in[8];
    float*       out      = (float*)d_out;

    int H = in_sizes[3];
    int E = in_sizes[6];
    int N = in_sizes[8];
    long long nhd = in_sizes[1];
    int D = (int)(nhd / ((long long)N * H));

    int s_count = N * H;
    if (s_count > MAX_S) return;

    const int TB = 256;

    // A: init scratch + out
    {
        int work = s_count > out_size ? s_count : out_size;
        init_kernel<<<(work + TB - 1) / TB, TB>>>(out, out_size, s_count);
    }

    bool fast = (H == 4 && D == 32 && nhd <= MAX_NHD && (nhd % 4) == 0);

    if (fast) {
        // A2: f32 -> f16 conversion of both matrices
        int total4 = (int)(nhd / 4);
        convert_kernel<<<(total4 + TB - 1) / TB, TB>>>(Q, K, total4);

        // B: half-warp per edge gather
        long long threads = (long long)((E + 1) / 2) * 32;
        int blocks = (int)((threads + TB - 1) / TB);
        edge_kernel_h<<<blocks, TB>>>(a, beta_raw, c, u, E);
    } else {
        long long total = (long long)E * H;
        edge_kernel_g<<<(int)((total + TB - 1) / TB), TB>>>(Q, K, a, beta_raw, c, u, E, H, D);
    }

    // C: node pass
    if (H == 4) {
        node_kernel_s<<<(N + TB - 1) / TB, TB>>>(batch, lam_raw, beta_raw, out, N);
    } else {
        node_kernel_g<<<(N + TB - 1) / TB, TB>>>(batch, lam_raw, beta_raw, out, N, H);
    }
}

// round 4
// speedup vs baseline: 2.6744x; 1.1369x over previous
#include <cuda_runtime.h>
#include <cuda_fp16.h>
#include <cuda_fp8.h>
#include <stdint.h>
#include <math.h>

// ---------------------------------------------------------------------------
// Static scratch (no runtime allocation allowed).
//   g_s : per-(node,head) exp-sum accumulator (float)
//   g_q8/g_k8 : e4m3 copies of Q2/K2 (row = H*D bytes = 128B = 1 line)
// ---------------------------------------------------------------------------
#define MAX_S   (4 * 1024 * 1024)
#define MAX_NHD (8 * 1024 * 1024)
__device__ float         g_s[MAX_S];
__device__ unsigned char g_q8[MAX_NHD];
__device__ unsigned char g_k8[MAX_NHD];

__device__ __forceinline__ float softplus_f(float x) {
    return log1pf(expf(x));
}

__device__ __forceinline__ __half2 fp8x2_to_h2(unsigned short s) {
    union { __half2_raw r; __half2 h; } cvt;
    cvt.r = __nv_cvt_fp8x2_to_halfraw2((__nv_fp8x2_storage_t)s, __NV_E4M3);
    return cvt.h;
}

// ---------------------------------------------------------------------------
// Kernel A (fused): zero g_s + out, convert Q/K f32 -> e4m3.
// Thread i handles elements [4i, 4i+4) of both matrices.
// ---------------------------------------------------------------------------
__global__ void prep_kernel(const float* __restrict__ Q,
                            const float* __restrict__ K,
                            float* __restrict__ out,
                            int out_size, int s_count, int total4) {
    int i = blockIdx.x * blockDim.x + threadIdx.x;
    if (i < s_count) g_s[i] = 0.0f;
    if (i < out_size) out[i] = 0.0f;
    if (i >= total4) return;
    float4 q = reinterpret_cast<const float4*>(Q)[i];
    float4 k = reinterpret_cast<const float4*>(K)[i];
    unsigned int qp =
        (unsigned int)__nv_cvt_float2_to_fp8x2(make_float2(q.x, q.y), __NV_SATFINITE, __NV_E4M3) |
        ((unsigned int)__nv_cvt_float2_to_fp8x2(make_float2(q.z, q.w), __NV_SATFINITE, __NV_E4M3) << 16);
    unsigned int kp =
        (unsigned int)__nv_cvt_float2_to_fp8x2(make_float2(k.x, k.y), __NV_SATFINITE, __NV_E4M3) |
        ((unsigned int)__nv_cvt_float2_to_fp8x2(make_float2(k.z, k.w), __NV_SATFINITE, __NV_E4M3) << 16);
    reinterpret_cast<unsigned int*>(g_q8)[i] = qp;
    reinterpret_cast<unsigned int*>(g_k8)[i] = kp;
}

// ---------------------------------------------------------------------------
// Kernel B (H=4, D=32, fp8): half-warp per edge.
// Row = 128 fp8 = 128B. Lane lw in [0,16) loads 8B of Q and K (uint2);
// lw covers head h = lw>>2, elems 8*lw .. 8*lw+7. Quad shuffle-reduce,
// quad leader does exp + atomicAdd into g_s.
// ---------------------------------------------------------------------------
__global__ void edge_kernel_8(const float* __restrict__ a,
                              const float* __restrict__ beta_raw,
                              const int* __restrict__ c,
                              const int* __restrict__ u,
                              int E) {
    int warp = (blockIdx.x * blockDim.x + threadIdx.x) >> 5;
    int lane = threadIdx.x & 31;
    int half_sel = lane >> 4;
    int lw = lane & 15;

    int e = warp * 2 + half_sel;
    bool active = (e < E);
    int es = active ? e : 0;

    int ci = c[es];
    int ui = u[es];

    uint2 qv = reinterpret_cast<const uint2*>(g_q8 + (size_t)ci * 128)[lw];
    uint2 kv = reinterpret_cast<const uint2*>(g_k8 + (size_t)ui * 128)[lw];

    __half2 acc = __float2half2_rn(0.0f);
    {
        __half2 q0 = fp8x2_to_h2((unsigned short)(qv.x & 0xffff));
        __half2 q1 = fp8x2_to_h2((unsigned short)(qv.x >> 16));
        __half2 k0 = fp8x2_to_h2((unsigned short)(kv.x & 0xffff));
        __half2 k1 = fp8x2_to_h2((unsigned short)(kv.x >> 16));
        acc = __hfma2(q0, k0, acc);
        acc = __hfma2(q1, k1, acc);
        __half2 q2 = fp8x2_to_h2((unsigned short)(qv.y & 0xffff));
        __half2 q3 = fp8x2_to_h2((unsigned short)(qv.y >> 16));
        __half2 k2 = fp8x2_to_h2((unsigned short)(kv.y & 0xffff));
        __half2 k3 = fp8x2_to_h2((unsigned short)(kv.y >> 16));
        acc = __hfma2(q2, k2, acc);
        acc = __hfma2(q3, k3, acc);
    }
    float fa = __low2float(acc) + __high2float(acc);

    // reduce within quad (4 lanes = one head's 32 elems)
    fa += __shfl_xor_sync(0xffffffffu, fa, 1);
    fa += __shfl_xor_sync(0xffffffffu, fa, 2);

    if (active && (lw & 3) == 0) {
        int h = lw >> 2;
        float beta = fminf(softplus_f(beta_raw[0]), 10.0f);
        float ell = fa * 0.17677669529663688f + a[h];   // 1/sqrt(32)
        atomicAdd(&g_s[(size_t)ci * 4 + h], __expf(beta * ell));
    }
}

// Generic fallback (any H, D) — f32 path, one thread per (edge, head)
__global__ void edge_kernel_g(const float* __restrict__ Q,
                              const float* __restrict__ K,
                              const float* __restrict__ a,
                              const float* __restrict__ beta_raw,
                              const int* __restrict__ c,
                              const int* __restrict__ u,
                              int E, int H, int D) {
    long long tid = (long long)blockIdx.x * blockDim.x + threadIdx.x;
    long long total = (long long)E * H;
    if (tid >= total) return;
    int e = (int)(tid / H);
    int h = (int)(tid % H);

    int ci = c[e];
    int ui = u[e];

    const float* q = Q + ((size_t)ci * H + h) * D;
    const float* k = K + ((size_t)ui * H + h) * D;
    float acc = 0.0f;
    for (int d = 0; d < D; d++) acc = fmaf(q[d], k[d], acc);

    float beta = fminf(softplus_f(beta_raw[0]), 10.0f);
    float ell = acc * rsqrtf((float)D) + a[h];
    atomicAdd(&g_s[(size_t)ci * H + h], __expf(beta * ell));
}

// ---------------------------------------------------------------------------
// Kernel C: per-node log + per-graph reduce via block-local smem, then one
// global atomic per (graph,head) per block (out_size <= 4096 path).
// ---------------------------------------------------------------------------
#define MAX_GH 4096
__global__ void node_kernel_sm(const int* __restrict__ batch,
                               const float* __restrict__ lam_raw,
                               const float* __restrict__ beta_raw,
                               float* __restrict__ out,
                               int N, int H, int gh) {
    __shared__ float sred[MAX_GH];
    for (int i = threadIdx.x; i < gh; i += blockDim.x) sred[i] = 0.0f;
    __syncthreads();

    float lam  = softplus_f(lam_raw[0]);
    float beta = fminf(softplus_f(beta_raw[0]), 10.0f);
    float coef = lam / beta;

    if (H == 4) {
        for (int n = blockIdx.x * blockDim.x + threadIdx.x; n < N;
             n += gridDim.x * blockDim.x) {
            float4 sv = reinterpret_cast<const float4*>(g_s)[n];
            int g = batch[n];
            float v0 = sv.x > 0.0f ? logf(sv.x) : 0.0f;
            float v1 = sv.y > 0.0f ? logf(sv.y) : 0.0f;
            float v2 = sv.z > 0.0f ? logf(sv.z) : 0.0f;
            float v3 = sv.w > 0.0f ? logf(sv.w) : 0.0f;
            atomicAdd(&sred[g * 4 + 0], v0);
            atomicAdd(&sred[g * 4 + 1], v1);
            atomicAdd(&sred[g * 4 + 2], v2);
            atomicAdd(&sred[g * 4 + 3], v3);
        }
    } else {
        for (int n = blockIdx.x * blockDim.x + threadIdx.x; n < N;
             n += gridDim.x * blockDim.x) {
            int g = batch[n];
            for (int h = 0; h < H; h++) {
                float s = g_s[(size_t)n * H + h];
                float v = s > 0.0f ? logf(s) : 0.0f;
                atomicAdd(&sred[g * H + h], v);
            }
        }
    }
    __syncthreads();
    for (int i = threadIdx.x; i < gh; i += blockDim.x) {
        float v = sred[i];
        if (v != 0.0f) atomicAdd(&out[i], coef * v);
    }
}

// Fallback: direct global atomics (only if out_size > MAX_GH)
__global__ void node_kernel_g(const int* __restrict__ batch,
                              const float* __restrict__ lam_raw,
                              const float* __restrict__ beta_raw,
                              float* __restrict__ out,
                              int N, int H) {
    int n = blockIdx.x * blockDim.x + threadIdx.x;
    if (n >= N) return;
    float lam  = softplus_f(lam_raw[0]);
    float beta = fminf(softplus_f(beta_raw[0]), 10.0f);
    float coef = lam / beta;
    int g = batch[n];
    for (int h = 0; h < H; h++) {
        float s = g_s[(size_t)n * H + h];
        float v = s > 0.0f ? logf(s) : 0.0f;
        atomicAdd(&out[g * H + h], coef * v);
    }
}

// ---------------------------------------------------------------------------
// Launch.  Inputs (metadata order):
//   0: G [4,4] f32 (unused)   1: Q2 [N,H,D] f32   2: K2 [N,H,D] f32
//   3: a_2 [H] f32   4: lambda_2_raw [1] f32   5: beta_2_raw [1] f32
//   6: c_2 [E] i32   7: u_2 [E] i32   8: batch [N] i32
// Output: [num_graphs, H] f32
// ---------------------------------------------------------------------------
extern "C" void kernel_launch(void* const* d_in, const int* in_sizes, int n_in,
                              void* d_out, int out_size) {
    const float* Q        = (const float*)d_in[1];
    const float* K        = (const float*)d_in[2];
    const float* a        = (const float*)d_in[3];
    const float* lam_raw  = (const float*)d_in[4];
    const float* beta_raw = (const float*)d_in[5];
    const int*   c        = (const int*)d_in[6];
    const int*   u        = (const int*)d_in[7];
    const int*   batch    = (const int*)d_in[8];
    float*       out      = (float*)d_out;

    int H = in_sizes[3];
    int E = in_sizes[6];
    int N = in_sizes[8];
    long long nhd = in_sizes[1];
    int D = (int)(nhd / ((long long)N * H));

    int s_count = N * H;
    if (s_count > MAX_S) return;

    const int TB = 256;
    bool fast = (H == 4 && D == 32 && nhd <= MAX_NHD && (nhd % 4) == 0);

    if (fast) {
        // A: fused zero + f32 -> e4m3 conversion
        int total4 = (int)(nhd / 4);
        int work = total4;
        if (s_count > work) work = s_count;
        if (out_size > work) work = out_size;
        prep_kernel<<<(work + TB - 1) / TB, TB>>>(Q, K, out, out_size, s_count, total4);

        // B: half-warp per edge fp8 gather
        long long threads = (long long)((E + 1) / 2) * 32;
        int blocks = (int)((threads + TB - 1) / TB);
        edge_kernel_8<<<blocks, TB>>>(a, beta_raw, c, u, E);
    } else {
        // zero + f32 edge path
        prep_kernel<<<((s_count > out_size ? s_count : out_size) + TB - 1) / TB, TB>>>(
            Q, K, out, out_size, s_count, 0);
        long long total = (long long)E * H;
        edge_kernel_g<<<(int)((total + TB - 1) / TB), TB>>>(Q, K, a, beta_raw, c, u, E, H, D);
    }

    // C: node pass
    if (out_size <= MAX_GH) {
        int blocks = (N + TB - 1) / TB;
        if (blocks > 120) blocks = 120;
        node_kernel_sm<<<blocks, TB>>>(batch, lam_raw, beta_raw, out, N, H, out_size);
    } else {
        node_kernel_g<<<(N + TB - 1) / TB, TB>>>(batch, lam_raw, beta_raw, out, N, H);
    }
}

// round 6
// speedup vs baseline: 2.7219x; 1.0178x over previous
#include <cuda_runtime.h>
#include <cuda_fp16.h>
#include <cuda_fp8.h>
#include <stdint.h>
#include <math.h>

// ---------------------------------------------------------------------------
// Static scratch (no runtime allocation allowed).
//   g_s : per-(node,head) exp-sum accumulator (float)
//   g_q8/g_k8 : e4m3 copies of Q2/K2 (row = H*D bytes = 128B = 1 line)
//   scalar params precomputed once in prep (hoists softplus out of hot loops)
// ---------------------------------------------------------------------------
#define MAX_S   (4 * 1024 * 1024)
#define MAX_NHD (8 * 1024 * 1024)
#define MAX_HB  64
__device__ float         g_s[MAX_S];
__device__ unsigned char g_q8[MAX_NHD];
__device__ unsigned char g_k8[MAX_NHD];
__device__ float         g_bs;          // beta / sqrt(D)
__device__ float         g_ba[MAX_HB];  // beta * a[h]
__device__ float         g_coef;        // lam / beta

__device__ __forceinline__ float softplus_f(float x) {
    return log1pf(expf(x));
}

__device__ __forceinline__ __half2 fp8x2_to_h2(unsigned short s) {
    union { __half2_raw r; __half2 h; } cvt;
    cvt.r = __nv_cvt_fp8x2_to_halfraw2((__nv_fp8x2_storage_t)s, __NV_E4M3);
    return cvt.h;
}

// ---------------------------------------------------------------------------
// Kernel A (fused): zero g_s + out, convert Q/K f32 -> e4m3, and (thread 0)
// precompute all scalar parameters.
// ---------------------------------------------------------------------------
__global__ void prep_kernel(const float* __restrict__ Q,
                            const float* __restrict__ K,
                            const float* __restrict__ a,
                            const float* __restrict__ lam_raw,
                            const float* __restrict__ beta_raw,
                            float* __restrict__ out,
                            int out_size, int s_count, int total4,
                            int H, int D) {
    int i = blockIdx.x * blockDim.x + threadIdx.x;
    if (i == 0) {
        float beta = fminf(softplus_f(beta_raw[0]), 10.0f);
        float lam  = softplus_f(lam_raw[0]);
        g_bs   = beta * rsqrtf((float)D);
        g_coef = lam / beta;
        int hb = H < MAX_HB ? H : MAX_HB;
        for (int h = 0; h < hb; h++) g_ba[h] = beta * a[h];
    }
    if (i < s_count) g_s[i] = 0.0f;
    if (i < out_size) out[i] = 0.0f;
    if (i >= total4) return;
    float4 q = reinterpret_cast<const float4*>(Q)[i];
    float4 k = reinterpret_cast<const float4*>(K)[i];
    unsigned int qp =
        (unsigned int)__nv_cvt_float2_to_fp8x2(make_float2(q.x, q.y), __NV_SATFINITE, __NV_E4M3) |
        ((unsigned int)__nv_cvt_float2_to_fp8x2(make_float2(q.z, q.w), __NV_SATFINITE, __NV_E4M3) << 16);
    unsigned int kp =
        (unsigned int)__nv_cvt_float2_to_fp8x2(make_float2(k.x, k.y), __NV_SATFINITE, __NV_E4M3) |
        ((unsigned int)__nv_cvt_float2_to_fp8x2(make_float2(k.z, k.w), __NV_SATFINITE, __NV_E4M3) << 16);
    reinterpret_cast<unsigned int*>(g_q8)[i] = qp;
    reinterpret_cast<unsigned int*>(g_k8)[i] = kp;
}

// ---------------------------------------------------------------------------
// Kernel B (H=4, D=32, fp8): half-warp per edge. Lane lw in [0,16) loads 8B
// of Q and K rows (1 line per row). Quad = one head; shuffle-reduce; quad
// leader: single __expf + RED. All scalar params preloaded.
// ---------------------------------------------------------------------------
__global__ void edge_kernel_8(const int* __restrict__ c,
                              const int* __restrict__ u,
                              int E) {
    int warp = (blockIdx.x * blockDim.x + threadIdx.x) >> 5;
    int lane = threadIdx.x & 31;
    int half_sel = lane >> 4;
    int lw = lane & 15;

    int e = warp * 2 + half_sel;
    bool active = (e < E);
    int es = active ? e : 0;

    int ci = c[es];
    int ui = u[es];

    uint2 qv = reinterpret_cast<const uint2*>(g_q8 + (size_t)ci * 128)[lw];
    uint2 kv = reinterpret_cast<const uint2*>(g_k8 + (size_t)ui * 128)[lw];

    __half2 acc = __float2half2_rn(0.0f);
    acc = __hfma2(fp8x2_to_h2((unsigned short)(qv.x & 0xffff)),
                  fp8x2_to_h2((unsigned short)(kv.x & 0xffff)), acc);
    acc = __hfma2(fp8x2_to_h2((unsigned short)(qv.x >> 16)),
                  fp8x2_to_h2((unsigned short)(kv.x >> 16)), acc);
    acc = __hfma2(fp8x2_to_h2((unsigned short)(qv.y & 0xffff)),
                  fp8x2_to_h2((unsigned short)(kv.y & 0xffff)), acc);
    acc = __hfma2(fp8x2_to_h2((unsigned short)(qv.y >> 16)),
                  fp8x2_to_h2((unsigned short)(kv.y >> 16)), acc);
    float fa = __low2float(acc) + __high2float(acc);

    fa += __shfl_xor_sync(0xffffffffu, fa, 1);
    fa += __shfl_xor_sync(0xffffffffu, fa, 2);

    if (active && (lw & 3) == 0) {
        int h = lw >> 2;
        float v = __expf(fmaf(fa, g_bs, g_ba[h]));
        atomicAdd(&g_s[(size_t)ci * 4 + h], v);
    }
}

// Generic fallback (any H, D) — f32 path, one thread per (edge, head)
__global__ void edge_kernel_g(const float* __restrict__ Q,
                              const float* __restrict__ K,
                              const float* __restrict__ a,
                              const float* __restrict__ beta_raw,
                              const int* __restrict__ c,
                              const int* __restrict__ u,
                              int E, int H, int D) {
    long long tid = (long long)blockIdx.x * blockDim.x + threadIdx.x;
    long long total = (long long)E * H;
    if (tid >= total) return;
    int e = (int)(tid / H);
    int h = (int)(tid % H);

    int ci = c[e];
    int ui = u[e];

    const float* q = Q + ((size_t)ci * H + h) * D;
    const float* k = K + ((size_t)ui * H + h) * D;
    float acc = 0.0f;
    for (int d = 0; d < D; d++) acc = fmaf(q[d], k[d], acc);

    float beta = fminf(softplus_f(beta_raw[0]), 10.0f);
    float ell = acc * rsqrtf((float)D) + a[h];
    atomicAdd(&g_s[(size_t)ci * H + h], __expf(beta * ell));
}

// ---------------------------------------------------------------------------
// Kernel C: per-node log + per-graph reduce via block-local smem, then one
// global atomic per (graph,head) per block.
// ---------------------------------------------------------------------------
#define MAX_GH 4096
__global__ void node_kernel_sm(const int* __restrict__ batch,
                               float* __restrict__ out,
                               int N, int H, int gh) {
    __shared__ float sred[MAX_GH];
    for (int i = threadIdx.x; i < gh; i += blockDim.x) sred[i] = 0.0f;
    __syncthreads();

    if (H == 4) {
        for (int n = blockIdx.x * blockDim.x + threadIdx.x; n < N;
             n += gridDim.x * blockDim.x) {
            float4 sv = reinterpret_cast<const float4*>(g_s)[n];
            int g = batch[n];
            float v0 = sv.x > 0.0f ? logf(sv.x) : 0.0f;
            float v1 = sv.y > 0.0f ? logf(sv.y) : 0.0f;
            float v2 = sv.z > 0.0f ? logf(sv.z) : 0.0f;
            float v3 = sv.w > 0.0f ? logf(sv.w) : 0.0f;
            atomicAdd(&sred[g * 4 + 0], v0);
            atomicAdd(&sred[g * 4 + 1], v1);
            atomicAdd(&sred[g * 4 + 2], v2);
            atomicAdd(&sred[g * 4 + 3], v3);
        }
    } else {
        for (int n = blockIdx.x * blockDim.x + threadIdx.x; n < N;
             n += gridDim.x * blockDim.x) {
            int g = batch[n];
            for (int h = 0; h < H; h++) {
                float s = g_s[(size_t)n * H + h];
                float v = s > 0.0f ? logf(s) : 0.0f;
                atomicAdd(&sred[g * H + h], v);
            }
        }
    }
    __syncthreads();
    float coef = g_coef;
    for (int i = threadIdx.x; i < gh; i += blockDim.x) {
        float v = sred[i];
        if (v != 0.0f) atomicAdd(&out[i], coef * v);
    }
}

// Fallback: direct global atomics (only if out_size > MAX_GH)
__global__ void node_kernel_g(const int* __restrict__ batch,
                              float* __restrict__ out,
                              int N, int H) {
    int n = blockIdx.x * blockDim.x + threadIdx.x;
    if (n >= N) return;
    float coef = g_coef;
    int g = batch[n];
    for (int h = 0; h < H; h++) {
        float s = g_s[(size_t)n * H + h];
        float v = s > 0.0f ? logf(s) : 0.0f;
        atomicAdd(&out[g * H + h], coef * v);
    }
}

// ---------------------------------------------------------------------------
// Launch.  Inputs (metadata order):
//   0: G [4,4] f32 (unused)   1: Q2 [N,H,D] f32   2: K2 [N,H,D] f32
//   3: a_2 [H] f32   4: lambda_2_raw [1] f32   5: beta_2_raw [1] f32
//   6: c_2 [E] i32   7: u_2 [E] i32   8: batch [N] i32
// Output: [num_graphs, H] f32
// ---------------------------------------------------------------------------
extern "C" void kernel_launch(void* const* d_in, const int* in_sizes, int n_in,
                              void* d_out, int out_size) {
    const float* Q        = (const float*)d_in[1];
    const float* K        = (const float*)d_in[2];
    const float* a        = (const float*)d_in[3];
    const float* lam_raw  = (const float*)d_in[4];
    const float* beta_raw = (const float*)d_in[5];
    const int*   c        = (const int*)d_in[6];
    const int*   u        = (const int*)d_in[7];
    const int*   batch    = (const int*)d_in[8];
    float*       out      = (float*)d_out;

    int H = in_sizes[3];
    int E = in_sizes[6];
    int N = in_sizes[8];
    long long nhd = in_sizes[1];
    int D = (int)(nhd / ((long long)N * H));

    int s_count = N * H;
    if (s_count > MAX_S) return;

    const int TB = 256;
    bool fast = (H == 4 && D == 32 && nhd <= MAX_NHD && (nhd % 4) == 0);

    if (fast) {
        int total4 = (int)(nhd / 4);
        int work = total4;
        if (s_count > work) work = s_count;
        if (out_size > work) work = out_size;
        prep_kernel<<<(work + TB - 1) / TB, TB>>>(Q, K, a, lam_raw, beta_raw,
                                                  out, out_size, s_count, total4, H, D);

        long long threads = (long long)((E + 1) / 2) * 32;
        int blocks = (int)((threads + TB - 1) / TB);
        edge_kernel_8<<<blocks, TB>>>(c, u, E);
    } else {
        prep_kernel<<<((s_count > out_size ? s_count : out_size) + TB - 1) / TB, TB>>>(
            Q, K, a, lam_raw, beta_raw, out, out_size, s_count, 0, H, D);
        long long total = (long long)E * H;
        edge_kernel_g<<<(int)((total + TB - 1) / TB), TB>>>(Q, K, a, beta_raw, c, u, E, H, D);
    }

    if (out_size <= MAX_GH) {
        int blocks = (N + TB - 1) / TB;
        if (blocks > 120) blocks = 120;
        node_kernel_sm<<<blocks, TB>>>(batch, out, N, H, out_size);
    } else {
        node_kernel_g<<<(N + TB - 1) / TB, TB>>>(batch, out, N, H);
    }
}

// round 7
// speedup vs baseline: 3.8007x; 1.3963x over previous
#include <cuda_runtime.h>
#include <cuda_fp16.h>
#include <cuda_fp8.h>
#include <stdint.h>
#include <math.h>

// ---------------------------------------------------------------------------
// Static scratch (no runtime allocation allowed).
//   g_s : per-(node,head) exp-sum accumulator (float)
//   g_q8/g_k8 : e4m3 copies of Q2/K2 (row = H*D bytes = 128B = 1 line)
//   scalar params precomputed once in prep
// ---------------------------------------------------------------------------
#define MAX_S   (4 * 1024 * 1024)
#define MAX_NHD (8 * 1024 * 1024)
#define MAX_HB  64
__device__ float         g_s[MAX_S];
__device__ unsigned char g_q8[MAX_NHD];
__device__ unsigned char g_k8[MAX_NHD];
__device__ float         g_bs;          // beta / sqrt(D)
__device__ float         g_ba[MAX_HB];  // beta * a[h]
__device__ float         g_coef;        // lam / beta

__device__ __forceinline__ float softplus_f(float x) {
    return log1pf(expf(x));
}

__device__ __forceinline__ __half2 fp8x2_to_h2(unsigned short s) {
    union { __half2_raw r; __half2 h; } cvt;
    cvt.r = __nv_cvt_fp8x2_to_halfraw2((__nv_fp8x2_storage_t)s, __NV_E4M3);
    return cvt.h;
}

// ---------------------------------------------------------------------------
// Kernel A (fused): zero g_s + out, convert Q/K f32 -> e4m3, precompute
// scalar params (thread 0).
// ---------------------------------------------------------------------------
__global__ void prep_kernel(const float* __restrict__ Q,
                            const float* __restrict__ K,
                            const float* __restrict__ a,
                            const float* __restrict__ lam_raw,
                            const float* __restrict__ beta_raw,
                            float* __restrict__ out,
                            int out_size, int s_count, int total4,
                            int H, int D) {
    int i = blockIdx.x * blockDim.x + threadIdx.x;
    if (i == 0) {
        float beta = fminf(softplus_f(beta_raw[0]), 10.0f);
        float lam  = softplus_f(lam_raw[0]);
        g_bs   = beta * rsqrtf((float)D);
        g_coef = lam / beta;
        int hb = H < MAX_HB ? H : MAX_HB;
        for (int h = 0; h < hb; h++) g_ba[h] = beta * a[h];
    }
    if (i < s_count) g_s[i] = 0.0f;
    if (i < out_size) out[i] = 0.0f;
    if (i >= total4) return;
    float4 q = reinterpret_cast<const float4*>(Q)[i];
    float4 k = reinterpret_cast<const float4*>(K)[i];
    unsigned int qp =
        (unsigned int)__nv_cvt_float2_to_fp8x2(make_float2(q.x, q.y), __NV_SATFINITE, __NV_E4M3) |
        ((unsigned int)__nv_cvt_float2_to_fp8x2(make_float2(q.z, q.w), __NV_SATFINITE, __NV_E4M3) << 16);
    unsigned int kp =
        (unsigned int)__nv_cvt_float2_to_fp8x2(make_float2(k.x, k.y), __NV_SATFINITE, __NV_E4M3) |
        ((unsigned int)__nv_cvt_float2_to_fp8x2(make_float2(k.z, k.w), __NV_SATFINITE, __NV_E4M3) << 16);
    reinterpret_cast<unsigned int*>(g_q8)[i] = qp;
    reinterpret_cast<unsigned int*>(g_k8)[i] = kp;
}

// ---------------------------------------------------------------------------
// Kernel B (H=4, D=32, fp8): 8 edges per warp, 16 lanes per edge.
// Indices loaded via 2 coalesced lane-parallel LDGs + shuffles; all 8 gather
// pairs issued in an unrolled prologue (MLP ~16) before any consumption.
// Quad = one head; shuffle-reduce; quad leader: __expf + RED into g_s.
// ---------------------------------------------------------------------------
__global__ void __launch_bounds__(256) edge_kernel_8(const int* __restrict__ c,
                                                     const int* __restrict__ u,
                                                     int E) {
    int warp = (blockIdx.x * blockDim.x + threadIdx.x) >> 5;
    int lane = threadIdx.x & 31;
    int half_sel = (lane >> 4) & 1;  // which edge of each pair
    int lw = lane & 15;              // lane within half-warp

    int base = warp * 8;
    if (base >= E) return;

    // lanes 0-7 load c[base+j], lanes 8-15 load u[base+j]; others idle.
    int j = lane & 7;
    int idx = base + j;
    if (idx >= E) idx = E - 1;                 // clamp (masked later)
    int v = 0;
    if (lane < 8)       v = c[idx];
    else if (lane < 16) v = u[idx];

    // Distribute indices + issue all 8 gather pairs up front.
    uint2 qv[4], kv[4];
    int   cis[4];
    bool  act[4];
#pragma unroll
    for (int i = 0; i < 4; i++) {
        int e = base + 2 * i + half_sel;
        act[i] = (e < E);
        int ci = __shfl_sync(0xffffffffu, v, 2 * i + half_sel);
        int ui = __shfl_sync(0xffffffffu, v, 8 + 2 * i + half_sel);
        cis[i] = ci;
        qv[i] = reinterpret_cast<const uint2*>(g_q8 + (size_t)ci * 128)[lw];
        kv[i] = reinterpret_cast<const uint2*>(g_k8 + (size_t)ui * 128)[lw];
    }

    float bs = g_bs;

#pragma unroll
    for (int i = 0; i < 4; i++) {
        __half2 acc = __float2half2_rn(0.0f);
        acc = __hfma2(fp8x2_to_h2((unsigned short)(qv[i].x & 0xffff)),
                      fp8x2_to_h2((unsigned short)(kv[i].x & 0xffff)), acc);
        acc = __hfma2(fp8x2_to_h2((unsigned short)(qv[i].x >> 16)),
                      fp8x2_to_h2((unsigned short)(kv[i].x >> 16)), acc);
        acc = __hfma2(fp8x2_to_h2((unsigned short)(qv[i].y & 0xffff)),
                      fp8x2_to_h2((unsigned short)(kv[i].y & 0xffff)), acc);
        acc = __hfma2(fp8x2_to_h2((unsigned short)(qv[i].y >> 16)),
                      fp8x2_to_h2((unsigned short)(kv[i].y >> 16)), acc);
        float fa = __low2float(acc) + __high2float(acc);

        fa += __shfl_xor_sync(0xffffffffu, fa, 1);
        fa += __shfl_xor_sync(0xffffffffu, fa, 2);

        if (act[i] && (lw & 3) == 0) {
            int h = lw >> 2;
            atomicAdd(&g_s[(size_t)cis[i] * 4 + h], __expf(fmaf(fa, bs, g_ba[h])));
        }
    }
}

// Generic fallback (any H, D) — f32 path, one thread per (edge, head)
__global__ void edge_kernel_g(const float* __restrict__ Q,
                              const float* __restrict__ K,
                              const float* __restrict__ a,
                              const float* __restrict__ beta_raw,
                              const int* __restrict__ c,
                              const int* __restrict__ u,
                              int E, int H, int D) {
    long long tid = (long long)blockIdx.x * blockDim.x + threadIdx.x;
    long long total = (long long)E * H;
    if (tid >= total) return;
    int e = (int)(tid / H);
    int h = (int)(tid % H);

    int ci = c[e];
    int ui = u[e];

    const float* q = Q + ((size_t)ci * H + h) * D;
    const float* k = K + ((size_t)ui * H + h) * D;
    float acc = 0.0f;
    for (int d = 0; d < D; d++) acc = fmaf(q[d], k[d], acc);

    float beta = fminf(softplus_f(beta_raw[0]), 10.0f);
    float ell = acc * rsqrtf((float)D) + a[h];
    atomicAdd(&g_s[(size_t)ci * H + h], __expf(beta * ell));
}

// ---------------------------------------------------------------------------
// Kernel C: per-node log + per-graph reduce via block-local smem, then one
// global atomic per (graph,head) per block.
// ---------------------------------------------------------------------------
#define MAX_GH 4096
__global__ void node_kernel_sm(const int* __restrict__ batch,
                               float* __restrict__ out,
                               int N, int H, int gh) {
    __shared__ float sred[MAX_GH];
    for (int i = threadIdx.x; i < gh; i += blockDim.x) sred[i] = 0.0f;
    __syncthreads();

    if (H == 4) {
        for (int n = blockIdx.x * blockDim.x + threadIdx.x; n < N;
             n += gridDim.x * blockDim.x) {
            float4 sv = reinterpret_cast<const float4*>(g_s)[n];
            int g = batch[n];
            float v0 = sv.x > 0.0f ? logf(sv.x) : 0.0f;
            float v1 = sv.y > 0.0f ? logf(sv.y) : 0.0f;
            float v2 = sv.z > 0.0f ? logf(sv.z) : 0.0f;
            float v3 = sv.w > 0.0f ? logf(sv.w) : 0.0f;
            atomicAdd(&sred[g * 4 + 0], v0);
            atomicAdd(&sred[g * 4 + 1], v1);
            atomicAdd(&sred[g * 4 + 2], v2);
            atomicAdd(&sred[g * 4 + 3], v3);
        }
    } else {
        for (int n = blockIdx.x * blockDim.x + threadIdx.x; n < N;
             n += gridDim.x * blockDim.x) {
            int g = batch[n];
            for (int h = 0; h < H; h++) {
                float s = g_s[(size_t)n * H + h];
                float v = s > 0.0f ? logf(s) : 0.0f;
                atomicAdd(&sred[g * H + h], v);
            }
        }
    }
    __syncthreads();
    float coef = g_coef;
    for (int i = threadIdx.x; i < gh; i += blockDim.x) {
        float v = sred[i];
        if (v != 0.0f) atomicAdd(&out[i], coef * v);
    }
}

// Fallback: direct global atomics (only if out_size > MAX_GH)
__global__ void node_kernel_g(const int* __restrict__ batch,
                              float* __restrict__ out,
                              int N, int H) {
    int n = blockIdx.x * blockDim.x + threadIdx.x;
    if (n >= N) return;
    float coef = g_coef;
    int g = batch[n];
    for (int h = 0; h < H; h++) {
        float s = g_s[(size_t)n * H + h];
        float v = s > 0.0f ? logf(s) : 0.0f;
        atomicAdd(&out[g * H + h], coef * v);
    }
}

// ---------------------------------------------------------------------------
// Launch.  Inputs (metadata order):
//   0: G [4,4] f32 (unused)   1: Q2 [N,H,D] f32   2: K2 [N,H,D] f32
//   3: a_2 [H] f32   4: lambda_2_raw [1] f32   5: beta_2_raw [1] f32
//   6: c_2 [E] i32   7: u_2 [E] i32   8: batch [N] i32
// Output: [num_graphs, H] f32
// ---------------------------------------------------------------------------
extern "C" void kernel_launch(void* const* d_in, const int* in_sizes, int n_in,
                              void* d_out, int out_size) {
    const float* Q        = (const float*)d_in[1];
    const float* K        = (const float*)d_in[2];
    const float* a        = (const float*)d_in[3];
    const float* lam_raw  = (const float*)d_in[4];
    const float* beta_raw = (const float*)d_in[5];
    const int*   c        = (const int*)d_in[6];
    const int*   u        = (const int*)d_in[7];
    const int*   batch    = (const int*)d_in[8];
    float*       out      = (float*)d_out;

    int H = in_sizes[3];
    int E = in_sizes[6];
    int N = in_sizes[8];
    long long nhd = in_sizes[1];
    int D = (int)(nhd / ((long long)N * H));

    int s_count = N * H;
    if (s_count > MAX_S) return;

    const int TB = 256;
    bool fast = (H == 4 && D == 32 && nhd <= MAX_NHD && (nhd % 4) == 0);

    if (fast) {
        int total4 = (int)(nhd / 4);
        int work = total4;
        if (s_count > work) work = s_count;
        if (out_size > work) work = out_size;
        prep_kernel<<<(work + TB - 1) / TB, TB>>>(Q, K, a, lam_raw, beta_raw,
                                                  out, out_size, s_count, total4, H, D);

        // 8 edges per warp
        long long warps = (E + 7) / 8;
        long long threads = warps * 32;
        int blocks = (int)((threads + TB - 1) / TB);
        edge_kernel_8<<<blocks, TB>>>(c, u, E);
    } else {
        prep_kernel<<<((s_count > out_size ? s_count : out_size) + TB - 1) / TB, TB>>>(
            Q, K, a, lam_raw, beta_raw, out, out_size, s_count, 0, H, D);
        long long total = (long long)E * H;
        edge_kernel_g<<<(int)((total + TB - 1) / TB), TB>>>(Q, K, a, beta_raw, c, u, E, H, D);
    }

    if (out_size <= MAX_GH) {
        int blocks = (N + TB - 1) / TB;
        if (blocks > 120) blocks = 120;
        node_kernel_sm<<<blocks, TB>>>(batch, out, N, H, out_size);
    } else {
        node_kernel_g<<<(N + TB - 1) / TB, TB>>>(batch, out, N, H);
    }
}

// round 8
// speedup vs baseline: 4.5288x; 1.1916x over previous
#include <cuda_runtime.h>
#include <cuda_fp16.h>
#include <cuda_fp8.h>
#include <stdint.h>
#include <math.h>

// ---------------------------------------------------------------------------
// Static scratch (no runtime allocation allowed).
//   g_s : per-(node,head) exp-sum accumulator (float)
//   g_q8/g_k8 : e4m3 copies of Q2/K2 (row = H*D bytes = 128B = 1 line)
//   scalar params precomputed once in prep
// ---------------------------------------------------------------------------
#define MAX_S   (4 * 1024 * 1024)
#define MAX_NHD (8 * 1024 * 1024)
#define MAX_HB  64
__device__ float         g_s[MAX_S];
__device__ unsigned char g_q8[MAX_NHD];
__device__ unsigned char g_k8[MAX_NHD];
__device__ float         g_bs;          // beta / sqrt(D)
__device__ float         g_ba[MAX_HB];  // beta * a[h]
__device__ float         g_coef;        // lam / beta

__device__ __forceinline__ float softplus_f(float x) {
    return log1pf(expf(x));
}

__device__ __forceinline__ __half2 fp8x2_to_h2(unsigned short s) {
    union { __half2_raw r; __half2 h; } cvt;
    cvt.r = __nv_cvt_fp8x2_to_halfraw2((__nv_fp8x2_storage_t)s, __NV_E4M3);
    return cvt.h;
}

// ---------------------------------------------------------------------------
// Kernel A (fused): zero g_s + out, convert Q/K f32 -> e4m3, precompute
// scalar params (thread 0).
// ---------------------------------------------------------------------------
__global__ void prep_kernel(const float* __restrict__ Q,
                            const float* __restrict__ K,
                            const float* __restrict__ a,
                            const float* __restrict__ lam_raw,
                            const float* __restrict__ beta_raw,
                            float* __restrict__ out,
                            int out_size, int s_count, int total4,
                            int H, int D) {
    int i = blockIdx.x * blockDim.x + threadIdx.x;
    if (i == 0) {
        float beta = fminf(softplus_f(beta_raw[0]), 10.0f);
        float lam  = softplus_f(lam_raw[0]);
        g_bs   = beta * rsqrtf((float)D);
        g_coef = lam / beta;
        int hb = H < MAX_HB ? H : MAX_HB;
        for (int h = 0; h < hb; h++) g_ba[h] = beta * a[h];
    }
    if (i < s_count) g_s[i] = 0.0f;
    if (i < out_size) out[i] = 0.0f;
    if (i >= total4) return;
    float4 q = reinterpret_cast<const float4*>(Q)[i];
    float4 k = reinterpret_cast<const float4*>(K)[i];
    unsigned int qp =
        (unsigned int)__nv_cvt_float2_to_fp8x2(make_float2(q.x, q.y), __NV_SATFINITE, __NV_E4M3) |
        ((unsigned int)__nv_cvt_float2_to_fp8x2(make_float2(q.z, q.w), __NV_SATFINITE, __NV_E4M3) << 16);
    unsigned int kp =
        (unsigned int)__nv_cvt_float2_to_fp8x2(make_float2(k.x, k.y), __NV_SATFINITE, __NV_E4M3) |
        ((unsigned int)__nv_cvt_float2_to_fp8x2(make_float2(k.z, k.w), __NV_SATFINITE, __NV_E4M3) << 16);
    reinterpret_cast<unsigned int*>(g_q8)[i] = qp;
    reinterpret_cast<unsigned int*>(g_k8)[i] = kp;
}

// ---------------------------------------------------------------------------
// Kernel B (H=4, D=32, fp8): 16 edges per warp, 8 lanes per edge.
// Lane l: sub = l>>3 selects one of 4 concurrent edges per pass, lw8 = l&7
// covers 16B of the 128B row (LDG.128). All 16 gather pairs (32 lines)
// issued in the prologue. One shfl_xor pairs the two lanes of each head;
// even lanes hold head h = lw8>>1. One MUFU + one RED per pass (16 lanes
// active, 16 distinct g_s addresses).
// ---------------------------------------------------------------------------
__global__ void __launch_bounds__(256) edge_kernel_16(const int* __restrict__ c,
                                                      const int* __restrict__ u,
                                                      int E) {
    int warp = (blockIdx.x * blockDim.x + threadIdx.x) >> 5;
    int lane = threadIdx.x & 31;
    int sub = lane >> 3;   // edge slot within a pass (0..3)
    int lw8 = lane & 7;    // lane within edge

    int base = warp * 16;
    if (base >= E) return;

    // lanes 0-15 load c[base+lane], lanes 16-31 load u[base+lane-16]
    int j = lane & 15;
    int idx = base + j;
    if (idx >= E) idx = E - 1;   // clamp; masked at the atomic
    int v = (lane < 16) ? c[idx] : u[idx];

    // Prologue: issue all 16 gather pairs (8 LDG.128 per lane, 32 lines/warp)
    uint4 qv[4], kv[4];
    int   cis[4];
    bool  act[4];
#pragma unroll
    for (int p = 0; p < 4; p++) {
        int eoff = p * 4 + sub;
        act[p] = (base + eoff < E);
        int ci = __shfl_sync(0xffffffffu, v, eoff);
        int ui = __shfl_sync(0xffffffffu, v, 16 + eoff);
        cis[p] = ci;
        qv[p] = reinterpret_cast<const uint4*>(g_q8 + (size_t)ci * 128)[lw8];
        kv[p] = reinterpret_cast<const uint4*>(g_k8 + (size_t)ui * 128)[lw8];
    }

    float bs = g_bs;
    int h = lw8 >> 1;
    float bah = g_ba[h];
    bool leader = ((lw8 & 1) == 0);

#pragma unroll
    for (int p = 0; p < 4; p++) {
        const unsigned int* qw = reinterpret_cast<const unsigned int*>(&qv[p]);
        const unsigned int* kw = reinterpret_cast<const unsigned int*>(&kv[p]);
        __half2 acc = __float2half2_rn(0.0f);
#pragma unroll
        for (int w = 0; w < 4; w++) {
            acc = __hfma2(fp8x2_to_h2((unsigned short)(qw[w] & 0xffff)),
                          fp8x2_to_h2((unsigned short)(kw[w] & 0xffff)), acc);
            acc = __hfma2(fp8x2_to_h2((unsigned short)(qw[w] >> 16)),
                          fp8x2_to_h2((unsigned short)(kw[w] >> 16)), acc);
        }
        float fa = __low2float(acc) + __high2float(acc);
        fa += __shfl_xor_sync(0xffffffffu, fa, 1);  // pair covers one head

        if (act[p] && leader) {
            atomicAdd(&g_s[(size_t)cis[p] * 4 + h], __expf(fmaf(fa, bs, bah)));
        }
    }
}

// Generic fallback (any H, D) — f32 path, one thread per (edge, head)
__global__ void edge_kernel_g(const float* __restrict__ Q,
                              const float* __restrict__ K,
                              const float* __restrict__ a,
                              const float* __restrict__ beta_raw,
                              const int* __restrict__ c,
                              const int* __restrict__ u,
                              int E, int H, int D) {
    long long tid = (long long)blockIdx.x * blockDim.x + threadIdx.x;
    long long total = (long long)E * H;
    if (tid >= total) return;
    int e = (int)(tid / H);
    int h = (int)(tid % H);

    int ci = c[e];
    int ui = u[e];

    const float* q = Q + ((size_t)ci * H + h) * D;
    const float* k = K + ((size_t)ui * H + h) * D;
    float acc = 0.0f;
    for (int d = 0; d < D; d++) acc = fmaf(q[d], k[d], acc);

    float beta = fminf(softplus_f(beta_raw[0]), 10.0f);
    float ell = acc * rsqrtf((float)D) + a[h];
    atomicAdd(&g_s[(size_t)ci * H + h], __expf(beta * ell));
}

// ---------------------------------------------------------------------------
// Kernel C: per-node log + per-graph reduce via block-local smem, then one
// global atomic per (graph,head) per block.
// ---------------------------------------------------------------------------
#define MAX_GH 4096
__global__ void node_kernel_sm(const int* __restrict__ batch,
                               float* __restrict__ out,
                               int N, int H, int gh) {
    __shared__ float sred[MAX_GH];
    for (int i = threadIdx.x; i < gh; i += blockDim.x) sred[i] = 0.0f;
    __syncthreads();

    if (H == 4) {
        for (int n = blockIdx.x * blockDim.x + threadIdx.x; n < N;
             n += gridDim.x * blockDim.x) {
            float4 sv = reinterpret_cast<const float4*>(g_s)[n];
            int g = batch[n];
            float v0 = sv.x > 0.0f ? logf(sv.x) : 0.0f;
            float v1 = sv.y > 0.0f ? logf(sv.y) : 0.0f;
            float v2 = sv.z > 0.0f ? logf(sv.z) : 0.0f;
            float v3 = sv.w > 0.0f ? logf(sv.w) : 0.0f;
            atomicAdd(&sred[g * 4 + 0], v0);
            atomicAdd(&sred[g * 4 + 1], v1);
            atomicAdd(&sred[g * 4 + 2], v2);
            atomicAdd(&sred[g * 4 + 3], v3);
        }
    } else {
        for (int n = blockIdx.x * blockDim.x + threadIdx.x; n < N;
             n += gridDim.x * blockDim.x) {
            int g = batch[n];
            for (int h = 0; h < H; h++) {
                float s = g_s[(size_t)n * H + h];
                float v = s > 0.0f ? logf(s) : 0.0f;
                atomicAdd(&sred[g * H + h], v);
            }
        }
    }
    __syncthreads();
    float coef = g_coef;
    for (int i = threadIdx.x; i < gh; i += blockDim.x) {
        float v = sred[i];
        if (v != 0.0f) atomicAdd(&out[i], coef * v);
    }
}

// Fallback: direct global atomics (only if out_size > MAX_GH)
__global__ void node_kernel_g(const int* __restrict__ batch,
                              float* __restrict__ out,
                              int N, int H) {
    int n = blockIdx.x * blockDim.x + threadIdx.x;
    if (n >= N) return;
    float coef = g_coef;
    int g = batch[n];
    for (int h = 0; h < H; h++) {
        float s = g_s[(size_t)n * H + h];
        float v = s > 0.0f ? logf(s) : 0.0f;
        atomicAdd(&out[g * H + h], coef * v);
    }
}

// ---------------------------------------------------------------------------
// Launch.  Inputs (metadata order):
//   0: G [4,4] f32 (unused)   1: Q2 [N,H,D] f32   2: K2 [N,H,D] f32
//   3: a_2 [H] f32   4: lambda_2_raw [1] f32   5: beta_2_raw [1] f32
//   6: c_2 [E] i32   7: u_2 [E] i32   8: batch [N] i32
// Output: [num_graphs, H] f32
// ---------------------------------------------------------------------------
extern "C" void kernel_launch(void* const* d_in, const int* in_sizes, int n_in,
                              void* d_out, int out_size) {
    const float* Q        = (const float*)d_in[1];
    const float* K        = (const float*)d_in[2];
    const float* a        = (const float*)d_in[3];
    const float* lam_raw  = (const float*)d_in[4];
    const float* beta_raw = (const float*)d_in[5];
    const int*   c        = (const int*)d_in[6];
    const int*   u        = (const int*)d_in[7];
    const int*   batch    = (const int*)d_in[8];
    float*       out      = (float*)d_out;

    int H = in_sizes[3];
    int E = in_sizes[6];
    int N = in_sizes[8];
    long long nhd = in_sizes[1];
    int D = (int)(nhd / ((long long)N * H));

    int s_count = N * H;
    if (s_count > MAX_S) return;

    const int TB = 256;
    bool fast = (H == 4 && D == 32 && nhd <= MAX_NHD && (nhd % 4) == 0);

    if (fast) {
        int total4 = (int)(nhd / 4);
        int work = total4;
        if (s_count > work) work = s_count;
        if (out_size > work) work = out_size;
        prep_kernel<<<(work + TB - 1) / TB, TB>>>(Q, K, a, lam_raw, beta_raw,
                                                  out, out_size, s_count, total4, H, D);

        // 16 edges per warp
        long long warps = (E + 15) / 16;
        long long threads = warps * 32;
        int blocks = (int)((threads + TB - 1) / TB);
        edge_kernel_16<<<blocks, TB>>>(c, u, E);
    } else {
        prep_kernel<<<((s_count > out_size ? s_count : out_size) + TB - 1) / TB, TB>>>(
            Q, K, a, lam_raw, beta_raw, out, out_size, s_count, 0, H, D);
        long long total = (long long)E * H;
        edge_kernel_g<<<(int)((total + TB - 1) / TB), TB>>>(Q, K, a, beta_raw, c, u, E, H, D);
    }

    if (out_size <= MAX_GH) {
        int blocks = (N + TB - 1) / TB;
        if (blocks > 120) blocks = 120;
        node_kernel_sm<<<blocks, TB>>>(batch, out, N, H, out_size);
    } else {
        node_kernel_g<<<(N + TB - 1) / TB, TB>>>(batch, out, N, H);
    }
}